// round 14
// baseline (speedup 1.0000x reference)
#include <cuda_runtime.h>
#include <cuda_bf16.h>
#include <math.h>

#define N_NODES  50000
#define N_EDGES  800000
#define N_GRAPHS 100
#define IN_DIM   100
#define D        128
#define N_ETYPES 4
#define N_STEPS  8
#define G3       384
#define NODE_TILE 16

// ---------------- scratch (device globals; ONLY referenced in device code) --
__device__ float g_h[N_NODES * D];
__device__ float g_tr[(size_t)N_ETYPES * N_NODES * D];
__device__ float g_a[N_NODES * D];
__device__ float g_WihT[D * G3];   // [k][j] = W_ih[j][k]
__device__ float g_WhhT[D * G3];
__device__ float g_pooled[N_GRAPHS * D];

#define LOG2E 1.4426950408889634f

__device__ __forceinline__ float sigmoid_acc(float x) {
    return 1.0f / (1.0f + exp2f(-LOG2E * x));
}
__device__ __forceinline__ float tanh_acc(float x) {
    float xc = fminf(fmaxf(x, -20.0f), 20.0f);
    float t = exp2f(2.0f * LOG2E * xc);
    return (t - 1.0f) / (t + 1.0f);
}

// ---------------- init ----------------
__global__ void pad_h_kernel(const float* __restrict__ features) {
    int idx = blockIdx.x * blockDim.x + threadIdx.x;
    if (idx >= N_NODES * D) return;
    int n = idx >> 7;
    int d = idx & 127;
    g_h[idx] = (d < IN_DIM) ? features[n * IN_DIM + d] : 0.0f;
}

__global__ void zero_a_kernel() {
    int idx = blockIdx.x * blockDim.x + threadIdx.x;
    if (idx < N_NODES * D) g_a[idx] = 0.0f;
}

// ROOT-CAUSE FIX: destination is the device symbol referenced INSIDE the
// kernel (never passed from host — host-side &g_WihT is a host-shadow
// address; on GB300 ATS that silently writes host memory).
__global__ void transpose_ih_kernel(const float* __restrict__ W) {
    int idx = blockIdx.x * blockDim.x + threadIdx.x;
    if (idx >= G3 * D) return;
    int r = idx >> 7;      // 0..383
    int k = idx & 127;     // 0..127
    g_WihT[k * G3 + r] = W[idx];
}
__global__ void transpose_hh_kernel(const float* __restrict__ W) {
    int idx = blockIdx.x * blockDim.x + threadIdx.x;
    if (idx >= G3 * D) return;
    int r = idx >> 7;
    int k = idx & 127;
    g_WhhT[k * G3 + r] = W[idx];
}

// ---------------- msg linear ----------------
__global__ void lin_msg_kernel(const float* __restrict__ W_msg, const float* __restrict__ b_msg) {
    __shared__ float hs[NODE_TILE][D];
    const int t  = blockIdx.z;
    const int j  = threadIdx.x;
    const int n0 = blockIdx.x * NODE_TILE;
    const float* WT = W_msg + (size_t)t * D * D;

    #pragma unroll
    for (int i = 0; i < NODE_TILE; i++)
        hs[i][j] = g_h[(size_t)(n0 + i) * D + j];
    __syncthreads();

    float acc[NODE_TILE];
    float b = b_msg[t * D + j];
    #pragma unroll
    for (int i = 0; i < NODE_TILE; i++) acc[i] = b;

    #pragma unroll 4
    for (int k = 0; k < D; k++) {
        float w = WT[k * D + j];
        #pragma unroll
        for (int i = 0; i < NODE_TILE; i++)
            acc[i] = fmaf(hs[i][k], w, acc[i]);
    }

    float* C = g_tr + (size_t)t * N_NODES * D;
    #pragma unroll
    for (int i = 0; i < NODE_TILE; i++)
        C[(size_t)(n0 + i) * D + j] = acc[i];
}

// ---------------- edge scatter ----------------
__global__ void scatter_kernel(const int* __restrict__ esrc, const int* __restrict__ edst,
                               const int* __restrict__ etype) {
    long long gtid = (long long)blockIdx.x * blockDim.x + threadIdx.x;
    if (gtid >= (long long)N_EDGES * D) return;
    int e = (int)(gtid >> 7);
    int f = (int)(gtid & 127);
    int s  = esrc[e];
    int d2 = edst[e];
    int t  = etype[e];
    float v = g_tr[((size_t)t * N_NODES + s) * D + f];
    atomicAdd(&g_a[(size_t)d2 * D + f], v);
}

// ---------------- fused GRU ----------------
__global__ void fused_gru_kernel(const float* __restrict__ b_ih, const float* __restrict__ b_hh) {
    __shared__ float as_[NODE_TILE][D];
    __shared__ float hs[NODE_TILE][D];
    __shared__ float rg[NODE_TILE][D];
    __shared__ float zg[NODE_TILE][D];
    const int j  = threadIdx.x;
    const int n0 = blockIdx.x * NODE_TILE;

    #pragma unroll
    for (int i = 0; i < NODE_TILE; i++) {
        as_[i][j] = g_a[(size_t)(n0 + i) * D + j];
        hs[i][j]  = g_h[(size_t)(n0 + i) * D + j];
    }
    __syncthreads();

    #pragma unroll
    for (int c = 0; c < 3; c++) {
        float gi[NODE_TILE], gh[NODE_TILE];
        float bi = b_ih[c * D + j];
        float bh = b_hh[c * D + j];
        #pragma unroll
        for (int i = 0; i < NODE_TILE; i++) { gi[i] = bi; gh[i] = bh; }

        const float* wi = g_WihT + c * D + j;   // device symbol, device code: OK
        const float* wh = g_WhhT + c * D + j;
        #pragma unroll 2
        for (int k = 0; k < D; k++) {
            float wik = wi[(size_t)k * G3];
            float whk = wh[(size_t)k * G3];
            #pragma unroll
            for (int i = 0; i < NODE_TILE; i++) {
                gi[i] = fmaf(as_[i][k], wik, gi[i]);
                gh[i] = fmaf(hs[i][k],  whk, gh[i]);
            }
        }

        if (c == 0) {
            #pragma unroll
            for (int i = 0; i < NODE_TILE; i++)
                rg[i][j] = sigmoid_acc(gi[i] + gh[i]);
        } else if (c == 1) {
            #pragma unroll
            for (int i = 0; i < NODE_TILE; i++)
                zg[i][j] = sigmoid_acc(gi[i] + gh[i]);
        } else {
            #pragma unroll
            for (int i = 0; i < NODE_TILE; i++) {
                float nn = tanh_acc(gi[i] + rg[i][j] * gh[i]);
                float z  = zg[i][j];
                g_h[(size_t)(n0 + i) * D + j] = (1.0f - z) * nn + z * hs[i][j];
            }
        }
        __syncthreads();
    }
}

// ---------------- pooling (binary search; gids proven sorted int32 [0,100)) -
__global__ void pool_kernel(const int* __restrict__ graph_ids) {
    int g = blockIdx.x;
    int d = threadIdx.x;
    int lo = 0, hi = N_NODES;
    while (lo < hi) { int mid = (lo + hi) >> 1; if (graph_ids[mid] < g) lo = mid + 1; else hi = mid; }
    int start = lo;
    hi = N_NODES;
    while (lo < hi) { int mid = (lo + hi) >> 1; if (graph_ids[mid] < g + 1) lo = mid + 1; else hi = mid; }
    int end = lo;
    float sum = 0.0f;
    for (int n = start; n < end; n++) sum += g_h[(size_t)n * D + d];
    float cnt = (float)(end - start);
    g_pooled[g * D + d] = sum / fmaxf(cnt, 1.0f);
}

// ---------------- classifier ----------------
__global__ void classifier_kernel(const float* __restrict__ W1, const float* __restrict__ b1,
                                  const float* __restrict__ W2, const float* __restrict__ b2,
                                  float* __restrict__ out) {
    __shared__ float ps[D];
    __shared__ float red[256];
    int g = blockIdx.x;
    int j = threadIdx.x;
    if (j < D) ps[j] = g_pooled[g * D + j];
    __syncthreads();
    float acc = 0.0f;
    const float* w = W1 + j * D;
    #pragma unroll 8
    for (int d = 0; d < D; d++) acc = fmaf(ps[d], w[d], acc);
    float hidden = fmaxf(acc + b1[j], 0.0f);
    red[j] = hidden * W2[j];
    __syncthreads();
    #pragma unroll
    for (int s = 128; s > 0; s >>= 1) {
        if (j < s) red[j] += red[j + s];
        __syncthreads();
    }
    if (j == 0) out[g] = sigmoid_acc(red[0] + b2[0]);
}

// ---------------- launch orchestration --------------------------------------
extern "C" void kernel_launch(void* const* d_in, const int* in_sizes, int n_in,
                              void* d_out, int out_size) {
    const float* features  = (const float*)d_in[0];
    const int*   edge_src  = (const int*)  d_in[1];
    const int*   edge_dst  = (const int*)  d_in[2];
    const int*   edge_types= (const int*)  d_in[3];
    const int*   graph_ids = (const int*)  d_in[4];
    const float* W_msg     = (const float*)d_in[5];
    const float* b_msg     = (const float*)d_in[6];
    const float* W_ih      = (const float*)d_in[7];
    const float* W_hh      = (const float*)d_in[8];
    const float* b_ih      = (const float*)d_in[9];
    const float* b_hh      = (const float*)d_in[10];
    const float* W1        = (const float*)d_in[11];
    const float* b1        = (const float*)d_in[12];
    const float* W2        = (const float*)d_in[13];
    const float* b2        = (const float*)d_in[14];
    float* out = (float*)d_out;

    pad_h_kernel<<<(N_NODES * D + 255) / 256, 256>>>(features);
    transpose_ih_kernel<<<(G3 * D + 255) / 256, 256>>>(W_ih);
    transpose_hh_kernel<<<(G3 * D + 255) / 256, 256>>>(W_hh);

    const int NBLK = N_NODES / NODE_TILE;
    const long long SC_THREADS = (long long)N_EDGES * D;
    const int SC_BLOCKS = (int)((SC_THREADS + 255) / 256);

    for (int step = 0; step < N_STEPS; step++) {
        lin_msg_kernel<<<dim3(NBLK, 1, N_ETYPES), D>>>(W_msg, b_msg);
        zero_a_kernel<<<(N_NODES * D + 255) / 256, 256>>>();
        scatter_kernel<<<SC_BLOCKS, 256>>>(edge_src, edge_dst, edge_types);
        fused_gru_kernel<<<NBLK, D>>>(b_ih, b_hh);
    }

    pool_kernel<<<N_GRAPHS, D>>>(graph_ids);
    classifier_kernel<<<N_GRAPHS, 256>>>(W1, b1, W2, b2, out);
}

// round 15
// speedup vs baseline: 1.8321x; 1.8321x over previous
#include <cuda_runtime.h>
#include <cuda_bf16.h>
#include <math.h>

#define N_NODES  50000
#define N_EDGES  800000
#define N_GRAPHS 100
#define IN_DIM   100
#define D        128
#define N_ETYPES 4
#define N_STEPS  8
#define G3       384
#define MT       64          // node tile per GEMM block
#define NBLK_G   782         // ceil(50000/64)

// ---------------- scratch (device symbols referenced ONLY in device code) ---
__device__ float g_h[N_NODES * D];
__device__ float g_tr[(size_t)N_ETYPES * N_NODES * D];
__device__ float g_a[N_NODES * D];
__device__ float g_WihT[D * G3];   // [k][j] = W_ih[j][k]
__device__ float g_WhhT[D * G3];
__device__ float g_rg[N_NODES * D];
__device__ float g_zg[N_NODES * D];
__device__ float g_gin[N_NODES * D];
__device__ float g_ghn[N_NODES * D];
__device__ float g_pooled[N_GRAPHS * D];

#define LOG2E 1.4426950408889634f

__device__ __forceinline__ float sigmoid_acc(float x) {
    return 1.0f / (1.0f + exp2f(-LOG2E * x));
}
__device__ __forceinline__ float tanh_acc(float x) {
    float xc = fminf(fmaxf(x, -20.0f), 20.0f);
    float t = exp2f(2.0f * LOG2E * xc);
    return (t - 1.0f) / (t + 1.0f);
}

// ---------------- init ----------------
__global__ void pad_h_kernel(const float* __restrict__ features) {
    int idx = blockIdx.x * blockDim.x + threadIdx.x;
    if (idx >= N_NODES * D) return;
    int n = idx >> 7;
    int d = idx & 127;
    g_h[idx] = (d < IN_DIM) ? features[n * IN_DIM + d] : 0.0f;
}

__global__ void zero_a_kernel() {
    int idx = blockIdx.x * blockDim.x + threadIdx.x;
    if (idx < (N_NODES * D) / 4)
        reinterpret_cast<float4*>(g_a)[idx] = make_float4(0.f, 0.f, 0.f, 0.f);
}

// W [G3 x 128] -> g_W*T [128 x G3]  (dst = device symbol inside kernel)
__global__ void transpose_ih_kernel(const float* __restrict__ W) {
    int idx = blockIdx.x * blockDim.x + threadIdx.x;
    if (idx >= G3 * D) return;
    int r = idx >> 7;
    int k = idx & 127;
    g_WihT[k * G3 + r] = W[idx];
}
__global__ void transpose_hh_kernel(const float* __restrict__ W) {
    int idx = blockIdx.x * blockDim.x + threadIdx.x;
    if (idx >= G3 * D) return;
    int r = idx >> 7;
    int k = idx & 127;
    g_WhhT[k * G3 + r] = W[idx];
}

// ---------------- msg GEMM: g_tr[t] = h @ W_msg[t] + b_msg[t] ----------------
// 256 threads, 64-node tile, microtile 8 rows x 4 cols, KT=32.
// Warp-constant row group -> a-loads are pure LDS broadcasts.
__global__ __launch_bounds__(256) void lin_msg_kernel(
    const float* __restrict__ W_msg, const float* __restrict__ b_msg)
{
    __shared__ float As[MT * 32];          // [row][k]
    __shared__ float Bs[32 * D];           // [k][j]
    const int tid  = threadIdx.x;
    const int t    = blockIdx.z;
    const int n0   = blockIdx.x * MT;
    const int rowg = (tid >> 5) * 8;       // warp-constant
    const int col4 = (tid & 31) * 4;

    const float* Wt = W_msg + (size_t)t * D * D;   // [k][j] native

    float acc[8][4];
    #pragma unroll
    for (int i = 0; i < 8; i++)
        #pragma unroll
        for (int jj = 0; jj < 4; jj++) acc[i][jj] = 0.0f;

    for (int kt = 0; kt < 4; kt++) {
        // load As: 64x32 floats = 128 f4, th x2
        #pragma unroll
        for (int x = 0; x < 2; x++) {
            int e = tid + x * 256;          // f4 idx 0..511
            int r  = e >> 3;
            int kq = e & 7;
            int grow = n0 + r;
            float4 v = make_float4(0.f, 0.f, 0.f, 0.f);
            if (grow < N_NODES)
                v = *reinterpret_cast<const float4*>(g_h + (size_t)grow * D + kt * 32 + kq * 4);
            *reinterpret_cast<float4*>(As + r * 32 + kq * 4) = v;
        }
        // load Bs: 32x128 floats = 1024 f4, th x4
        #pragma unroll
        for (int x = 0; x < 4; x++) {
            int e = tid + x * 256;
            int k  = e >> 5;
            int j4 = (e & 31) * 4;
            *reinterpret_cast<float4*>(Bs + k * D + j4) =
                *reinterpret_cast<const float4*>(Wt + (size_t)(kt * 32 + k) * D + j4);
        }
        __syncthreads();

        #pragma unroll
        for (int k = 0; k < 32; k++) {
            float4 w = *reinterpret_cast<const float4*>(Bs + k * D + col4);
            #pragma unroll
            for (int i = 0; i < 8; i++) {
                float a = As[(rowg + i) * 32 + k];   // broadcast
                acc[i][0] = fmaf(a, w.x, acc[i][0]);
                acc[i][1] = fmaf(a, w.y, acc[i][1]);
                acc[i][2] = fmaf(a, w.z, acc[i][2]);
                acc[i][3] = fmaf(a, w.w, acc[i][3]);
            }
        }
        __syncthreads();
    }

    float4 b = *reinterpret_cast<const float4*>(b_msg + t * D + col4);
    float* C = g_tr + (size_t)t * N_NODES * D;
    #pragma unroll
    for (int i = 0; i < 8; i++) {
        int grow = n0 + rowg + i;
        if (grow < N_NODES) {
            float4 o = make_float4(acc[i][0] + b.x, acc[i][1] + b.y,
                                   acc[i][2] + b.z, acc[i][3] + b.w);
            *reinterpret_cast<float4*>(C + (size_t)grow * D + col4) = o;
        }
    }
}

// ---------------- edge scatter: warp/edge, LDG.128 + red.v4 -----------------
__global__ void scatter_kernel(const int* __restrict__ esrc, const int* __restrict__ edst,
                               const int* __restrict__ etype) {
    long long gtid = (long long)blockIdx.x * blockDim.x + threadIdx.x;
    int e    = (int)(gtid >> 5);
    int lane = (int)(gtid & 31);
    if (e >= N_EDGES) return;
    int s  = esrc[e];
    int d2 = edst[e];
    int t  = etype[e];
    float4 v = *reinterpret_cast<const float4*>(
        g_tr + ((size_t)t * N_NODES + s) * D + lane * 4);
    float* out = g_a + (size_t)d2 * D + lane * 4;
    asm volatile("red.global.add.v4.f32 [%0], {%1, %2, %3, %4};"
                 :: "l"(out), "f"(v.x), "f"(v.y), "f"(v.z), "f"(v.w)
                 : "memory");
}

// ---------------- GRU gates GEMM ---------------------------------------------
// grid (NBLK_G, 3). y = gate chunk c.
// c<2:  S = a@WihT_c + h@WhhT_c + b  -> sigmoid -> g_rg / g_zg
// c==2: gin, ghn stored raw (combine applies r).
__global__ __launch_bounds__(256) void gru_gates_kernel(
    const float* __restrict__ b_ih, const float* __restrict__ b_hh)
{
    __shared__ float AsA[MT * 32];
    __shared__ float AsH[MT * 32];
    __shared__ float BsI[32 * D];
    __shared__ float BsH[32 * D];
    const int tid  = threadIdx.x;
    const int c    = blockIdx.y;
    const int n0   = blockIdx.x * MT;
    const int rowg = (tid >> 5) * 8;
    const int col4 = (tid & 31) * 4;

    float gi[8][4], gh[8][4];
    #pragma unroll
    for (int i = 0; i < 8; i++)
        #pragma unroll
        for (int jj = 0; jj < 4; jj++) { gi[i][jj] = 0.0f; gh[i][jj] = 0.0f; }

    for (int kt = 0; kt < 4; kt++) {
        #pragma unroll
        for (int x = 0; x < 2; x++) {
            int e = tid + x * 256;
            int r  = e >> 3;
            int kq = e & 7;
            int grow = n0 + r;
            float4 va = make_float4(0.f, 0.f, 0.f, 0.f);
            float4 vh = make_float4(0.f, 0.f, 0.f, 0.f);
            if (grow < N_NODES) {
                va = *reinterpret_cast<const float4*>(g_a + (size_t)grow * D + kt * 32 + kq * 4);
                vh = *reinterpret_cast<const float4*>(g_h + (size_t)grow * D + kt * 32 + kq * 4);
            }
            *reinterpret_cast<float4*>(AsA + r * 32 + kq * 4) = va;
            *reinterpret_cast<float4*>(AsH + r * 32 + kq * 4) = vh;
        }
        #pragma unroll
        for (int x = 0; x < 4; x++) {
            int e = tid + x * 256;
            int k  = e >> 5;
            int j4 = (e & 31) * 4;
            size_t off = (size_t)(kt * 32 + k) * G3 + c * D + j4;
            *reinterpret_cast<float4*>(BsI + k * D + j4) =
                *reinterpret_cast<const float4*>(g_WihT + off);
            *reinterpret_cast<float4*>(BsH + k * D + j4) =
                *reinterpret_cast<const float4*>(g_WhhT + off);
        }
        __syncthreads();

        #pragma unroll
        for (int k = 0; k < 32; k++) {
            float4 wi = *reinterpret_cast<const float4*>(BsI + k * D + col4);
            float4 wh = *reinterpret_cast<const float4*>(BsH + k * D + col4);
            #pragma unroll
            for (int i = 0; i < 8; i++) {
                float a = AsA[(rowg + i) * 32 + k];
                float h = AsH[(rowg + i) * 32 + k];
                gi[i][0] = fmaf(a, wi.x, gi[i][0]); gh[i][0] = fmaf(h, wh.x, gh[i][0]);
                gi[i][1] = fmaf(a, wi.y, gi[i][1]); gh[i][1] = fmaf(h, wh.y, gh[i][1]);
                gi[i][2] = fmaf(a, wi.z, gi[i][2]); gh[i][2] = fmaf(h, wh.z, gh[i][2]);
                gi[i][3] = fmaf(a, wi.w, gi[i][3]); gh[i][3] = fmaf(h, wh.w, gh[i][3]);
            }
        }
        __syncthreads();
    }

    float4 bi = *reinterpret_cast<const float4*>(b_ih + c * D + col4);
    float4 bh = *reinterpret_cast<const float4*>(b_hh + c * D + col4);

    if (c < 2) {
        float* dst = (c == 0) ? g_rg : g_zg;
        #pragma unroll
        for (int i = 0; i < 8; i++) {
            int grow = n0 + rowg + i;
            if (grow < N_NODES) {
                float4 o;
                o.x = sigmoid_acc(gi[i][0] + bi.x + gh[i][0] + bh.x);
                o.y = sigmoid_acc(gi[i][1] + bi.y + gh[i][1] + bh.y);
                o.z = sigmoid_acc(gi[i][2] + bi.z + gh[i][2] + bh.z);
                o.w = sigmoid_acc(gi[i][3] + bi.w + gh[i][3] + bh.w);
                *reinterpret_cast<float4*>(dst + (size_t)grow * D + col4) = o;
            }
        }
    } else {
        #pragma unroll
        for (int i = 0; i < 8; i++) {
            int grow = n0 + rowg + i;
            if (grow < N_NODES) {
                float4 oi = make_float4(gi[i][0] + bi.x, gi[i][1] + bi.y,
                                        gi[i][2] + bi.z, gi[i][3] + bi.w);
                float4 oh = make_float4(gh[i][0] + bh.x, gh[i][1] + bh.y,
                                        gh[i][2] + bh.z, gh[i][3] + bh.w);
                *reinterpret_cast<float4*>(g_gin + (size_t)grow * D + col4) = oi;
                *reinterpret_cast<float4*>(g_ghn + (size_t)grow * D + col4) = oh;
            }
        }
    }
}

// ---------------- GRU combine: h = (1-z)*tanh(gin + r*ghn) + z*h -------------
__global__ void gru_combine_kernel() {
    int idx = blockIdx.x * blockDim.x + threadIdx.x;
    if (idx >= (N_NODES * D) / 4) return;
    float4 r  = reinterpret_cast<const float4*>(g_rg)[idx];
    float4 z  = reinterpret_cast<const float4*>(g_zg)[idx];
    float4 in = reinterpret_cast<const float4*>(g_gin)[idx];
    float4 hn = reinterpret_cast<const float4*>(g_ghn)[idx];
    float4 h  = reinterpret_cast<const float4*>(g_h)[idx];
    float4 o;
    o.x = (1.0f - z.x) * tanh_acc(in.x + r.x * hn.x) + z.x * h.x;
    o.y = (1.0f - z.y) * tanh_acc(in.y + r.y * hn.y) + z.y * h.y;
    o.z = (1.0f - z.z) * tanh_acc(in.z + r.z * hn.z) + z.z * h.z;
    o.w = (1.0f - z.w) * tanh_acc(in.w + r.w * hn.w) + z.w * h.w;
    reinterpret_cast<float4*>(g_h)[idx] = o;
}

// ---------------- pooling (graph_ids sorted int32 in [0,100)) ----------------
__global__ void pool_kernel(const int* __restrict__ graph_ids) {
    int g = blockIdx.x;
    int d = threadIdx.x;
    int lo = 0, hi = N_NODES;
    while (lo < hi) { int mid = (lo + hi) >> 1; if (graph_ids[mid] < g) lo = mid + 1; else hi = mid; }
    int start = lo;
    hi = N_NODES;
    while (lo < hi) { int mid = (lo + hi) >> 1; if (graph_ids[mid] < g + 1) lo = mid + 1; else hi = mid; }
    int end = lo;
    float sum = 0.0f;
    for (int n = start; n < end; n++) sum += g_h[(size_t)n * D + d];
    float cnt = (float)(end - start);
    g_pooled[g * D + d] = sum / fmaxf(cnt, 1.0f);
}

// ---------------- classifier --------------------------------------------------
__global__ void classifier_kernel(const float* __restrict__ W1, const float* __restrict__ b1,
                                  const float* __restrict__ W2, const float* __restrict__ b2,
                                  float* __restrict__ out) {
    __shared__ float ps[D];
    __shared__ float red[256];
    int g = blockIdx.x;
    int j = threadIdx.x;
    if (j < D) ps[j] = g_pooled[g * D + j];
    __syncthreads();
    float acc = 0.0f;
    const float* w = W1 + j * D;
    #pragma unroll 8
    for (int d = 0; d < D; d++) acc = fmaf(ps[d], w[d], acc);
    float hidden = fmaxf(acc + b1[j], 0.0f);
    red[j] = hidden * W2[j];
    __syncthreads();
    #pragma unroll
    for (int s = 128; s > 0; s >>= 1) {
        if (j < s) red[j] += red[j + s];
        __syncthreads();
    }
    if (j == 0) out[g] = sigmoid_acc(red[0] + b2[0]);
}

// ---------------- launch orchestration ----------------------------------------
extern "C" void kernel_launch(void* const* d_in, const int* in_sizes, int n_in,
                              void* d_out, int out_size) {
    const float* features  = (const float*)d_in[0];
    const int*   edge_src  = (const int*)  d_in[1];
    const int*   edge_dst  = (const int*)  d_in[2];
    const int*   edge_types= (const int*)  d_in[3];
    const int*   graph_ids = (const int*)  d_in[4];
    const float* W_msg     = (const float*)d_in[5];
    const float* b_msg     = (const float*)d_in[6];
    const float* W_ih      = (const float*)d_in[7];
    const float* W_hh      = (const float*)d_in[8];
    const float* b_ih      = (const float*)d_in[9];
    const float* b_hh      = (const float*)d_in[10];
    const float* W1        = (const float*)d_in[11];
    const float* b1        = (const float*)d_in[12];
    const float* W2        = (const float*)d_in[13];
    const float* b2        = (const float*)d_in[14];
    float* out = (float*)d_out;

    pad_h_kernel<<<(N_NODES * D + 255) / 256, 256>>>(features);
    transpose_ih_kernel<<<(G3 * D + 255) / 256, 256>>>(W_ih);
    transpose_hh_kernel<<<(G3 * D + 255) / 256, 256>>>(W_hh);

    const int SC_BLOCKS = (int)(((long long)N_EDGES * 32 + 255) / 256);  // 100000
    const int CB_BLOCKS = (N_NODES * D / 4 + 255) / 256;

    for (int step = 0; step < N_STEPS; step++) {
        lin_msg_kernel<<<dim3(NBLK_G, 1, N_ETYPES), 256>>>(W_msg, b_msg);
        zero_a_kernel<<<(N_NODES * D / 4 + 255) / 256, 256>>>();
        scatter_kernel<<<SC_BLOCKS, 256>>>(edge_src, edge_dst, edge_types);
        gru_gates_kernel<<<dim3(NBLK_G, 3), 256>>>(b_ih, b_hh);
        gru_combine_kernel<<<CB_BLOCKS, 256>>>();
    }

    pool_kernel<<<N_GRAPHS, D>>>(graph_ids);
    classifier_kernel<<<N_GRAPHS, 256>>>(W1, b1, W2, b2, out);
}

// round 16
// speedup vs baseline: 2.2705x; 1.2393x over previous
#include <cuda_runtime.h>
#include <cuda_bf16.h>
#include <math.h>
#include <mma.h>

using namespace nvcuda;

#define N_NODES  50000
#define N_EDGES  800000
#define N_GRAPHS 100
#define IN_DIM   100
#define D        128
#define N_ETYPES 4
#define N_STEPS  8
#define G3       384
#define MT       64
#define NBLK_G   782         // ceil(50000/64)

// smem staging strides (padded)
#define LDA 36               // 32 + 4
#define LDB 132              // 128 + 4
#define LDC 132

// ---------------- scratch (device symbols referenced ONLY in device code) ---
__device__ float g_h[N_NODES * D];
__device__ float g_tr[(size_t)N_ETYPES * N_NODES * D];
__device__ float g_a[N_NODES * D];
__device__ float g_WihT[D * G3];   // [k][j] = W_ih[j][k]
__device__ float g_WhhT[D * G3];
__device__ float g_rg[N_NODES * D];
__device__ float g_zg[N_NODES * D];
__device__ float g_gin[N_NODES * D];
__device__ float g_ghn[N_NODES * D];
__device__ float g_pooled[N_GRAPHS * D];

#define LOG2E 1.4426950408889634f

__device__ __forceinline__ float sigmoid_acc(float x) {
    return 1.0f / (1.0f + exp2f(-LOG2E * x));
}
__device__ __forceinline__ float tanh_acc(float x) {
    float xc = fminf(fmaxf(x, -20.0f), 20.0f);
    float t = exp2f(2.0f * LOG2E * xc);
    return (t - 1.0f) / (t + 1.0f);
}

// ---------------- init ----------------
__global__ void pad_h_kernel(const float* __restrict__ features) {
    int idx = blockIdx.x * blockDim.x + threadIdx.x;
    if (idx >= N_NODES * D) return;
    int n = idx >> 7;
    int d = idx & 127;
    g_h[idx] = (d < IN_DIM) ? features[n * IN_DIM + d] : 0.0f;
}

__global__ void zero_a_kernel() {
    int idx = blockIdx.x * blockDim.x + threadIdx.x;
    if (idx < (N_NODES * D) / 4)
        reinterpret_cast<float4*>(g_a)[idx] = make_float4(0.f, 0.f, 0.f, 0.f);
}

__global__ void transpose_ih_kernel(const float* __restrict__ W) {
    int idx = blockIdx.x * blockDim.x + threadIdx.x;
    if (idx >= G3 * D) return;
    int r = idx >> 7;
    int k = idx & 127;
    g_WihT[k * G3 + r] = W[idx];
}
__global__ void transpose_hh_kernel(const float* __restrict__ W) {
    int idx = blockIdx.x * blockDim.x + threadIdx.x;
    if (idx >= G3 * D) return;
    int r = idx >> 7;
    int k = idx & 127;
    g_WhhT[k * G3 + r] = W[idx];
}

// ---------------- msg GEMM (tf32 wmma): g_tr[t] = h @ W_msg[t] + b_msg[t] ---
// 256 thr, tile 64x128, 8 warps = 4(M) x 2(N-half), 4 frags/warp, K-chunk 32.
__global__ __launch_bounds__(256) void lin_msg_kernel(
    const float* __restrict__ W_msg, const float* __restrict__ b_msg)
{
    __shared__ float sm[MT * LDC];     // 8448 floats; As+Bs then reused as Cs
    float* As = sm;                    // 64 x LDA
    float* Bs = sm + MT * LDA;         // 32 x LDB
    float* Cs = sm;                    // 64 x LDC

    const int tid = threadIdx.x;
    const int t   = blockIdx.z;
    const int n0  = blockIdx.x * MT;
    const int w   = tid >> 5;
    const int wm  = w & 3;
    const int wn  = w >> 2;

    const float* Wt = W_msg + (size_t)t * D * D;

    wmma::fragment<wmma::accumulator, 16, 16, 8, float> c[4];
    #pragma unroll
    for (int i = 0; i < 4; i++) wmma::fill_fragment(c[i], 0.0f);

    for (int kt = 0; kt < 4; kt++) {
        #pragma unroll
        for (int x = 0; x < 2; x++) {
            int e = tid + x * 256;
            int r = e >> 3, kq = e & 7;
            int grow = n0 + r;
            float4 v = make_float4(0.f, 0.f, 0.f, 0.f);
            if (grow < N_NODES)
                v = *reinterpret_cast<const float4*>(g_h + (size_t)grow * D + kt * 32 + kq * 4);
            *reinterpret_cast<float4*>(As + r * LDA + kq * 4) = v;
        }
        #pragma unroll
        for (int x = 0; x < 4; x++) {
            int e = tid + x * 256;
            int k = e >> 5, j4 = (e & 31) * 4;
            *reinterpret_cast<float4*>(Bs + k * LDB + j4) =
                *reinterpret_cast<const float4*>(Wt + (size_t)(kt * 32 + k) * D + j4);
        }
        __syncthreads();

        #pragma unroll
        for (int ks = 0; ks < 4; ks++) {
            wmma::fragment<wmma::matrix_a, 16, 16, 8, wmma::precision::tf32, wmma::row_major> a;
            wmma::load_matrix_sync(a, As + wm * 16 * LDA + ks * 8, LDA);
            #pragma unroll
            for (int i = 0; i < a.num_elements; i++) a.x[i] = wmma::__float_to_tf32(a.x[i]);
            #pragma unroll
            for (int nt = 0; nt < 4; nt++) {
                wmma::fragment<wmma::matrix_b, 16, 16, 8, wmma::precision::tf32, wmma::row_major> b;
                wmma::load_matrix_sync(b, Bs + ks * 8 * LDB + wn * 64 + nt * 16, LDB);
                #pragma unroll
                for (int i = 0; i < b.num_elements; i++) b.x[i] = wmma::__float_to_tf32(b.x[i]);
                wmma::mma_sync(c[nt], a, b, c[nt]);
            }
        }
        __syncthreads();
    }

    #pragma unroll
    for (int nt = 0; nt < 4; nt++)
        wmma::store_matrix_sync(Cs + wm * 16 * LDC + wn * 64 + nt * 16, c[nt], LDC, wmma::mem_row_major);
    __syncthreads();

    float* C = g_tr + (size_t)t * N_NODES * D;
    #pragma unroll
    for (int x = 0; x < 8; x++) {
        int e = tid + x * 256;          // f4 idx over 64*32
        int r = e >> 5, j4 = (e & 31) * 4;
        int grow = n0 + r;
        if (grow < N_NODES) {
            float4 v = *reinterpret_cast<const float4*>(Cs + r * LDC + j4);
            float4 b = *reinterpret_cast<const float4*>(b_msg + t * D + j4);
            v.x += b.x; v.y += b.y; v.z += b.z; v.w += b.w;
            *reinterpret_cast<float4*>(C + (size_t)grow * D + j4) = v;
        }
    }
}

// ---------------- GRU gates GEMM (tf32 wmma) ---------------------------------
// grid (NBLK_G, 4):
//  y=0: r = sigmoid([a|h] @ [WihT;WhhT] chunk0 + bi0+bh0)   (K=256)
//  y=1: z = sigmoid(chunk1)                                  (K=256)
//  y=2: gin = a @ WihT chunk2 + bi2                          (K=128)
//  y=3: ghn = h @ WhhT chunk2 + bh2                          (K=128)
__global__ __launch_bounds__(256) void gru_gates_kernel(
    const float* __restrict__ b_ih, const float* __restrict__ b_hh)
{
    __shared__ float sm[MT * LDC];
    float* As = sm;
    float* Bs = sm + MT * LDA;
    float* Cs = sm;

    const int tid = threadIdx.x;
    const int y   = blockIdx.y;
    const int n0  = blockIdx.x * MT;
    const int w   = tid >> 5;
    const int wm  = w & 3;
    const int wn  = w >> 2;

    wmma::fragment<wmma::accumulator, 16, 16, 8, float> c[4];
    #pragma unroll
    for (int i = 0; i < 4; i++) wmma::fill_fragment(c[i], 0.0f);

    const int nkt = (y < 2) ? 8 : 4;
    for (int kt = 0; kt < nkt; kt++) {
        const float* Asrc;
        const float* Bsrc;
        int koff, bcol;
        if (y < 2) {
            Asrc = (kt < 4) ? g_a : g_h;
            Bsrc = (kt < 4) ? g_WihT : g_WhhT;
            koff = (kt & 3) * 32;
            bcol = y * D;
        } else {
            Asrc = (y == 2) ? g_a : g_h;
            Bsrc = (y == 2) ? g_WihT : g_WhhT;
            koff = kt * 32;
            bcol = 2 * D;
        }

        #pragma unroll
        for (int x = 0; x < 2; x++) {
            int e = tid + x * 256;
            int r = e >> 3, kq = e & 7;
            int grow = n0 + r;
            float4 v = make_float4(0.f, 0.f, 0.f, 0.f);
            if (grow < N_NODES)
                v = *reinterpret_cast<const float4*>(Asrc + (size_t)grow * D + koff + kq * 4);
            *reinterpret_cast<float4*>(As + r * LDA + kq * 4) = v;
        }
        #pragma unroll
        for (int x = 0; x < 4; x++) {
            int e = tid + x * 256;
            int k = e >> 5, j4 = (e & 31) * 4;
            *reinterpret_cast<float4*>(Bs + k * LDB + j4) =
                *reinterpret_cast<const float4*>(Bsrc + (size_t)(koff + k) * G3 + bcol + j4);
        }
        __syncthreads();

        #pragma unroll
        for (int ks = 0; ks < 4; ks++) {
            wmma::fragment<wmma::matrix_a, 16, 16, 8, wmma::precision::tf32, wmma::row_major> a;
            wmma::load_matrix_sync(a, As + wm * 16 * LDA + ks * 8, LDA);
            #pragma unroll
            for (int i = 0; i < a.num_elements; i++) a.x[i] = wmma::__float_to_tf32(a.x[i]);
            #pragma unroll
            for (int nt = 0; nt < 4; nt++) {
                wmma::fragment<wmma::matrix_b, 16, 16, 8, wmma::precision::tf32, wmma::row_major> b;
                wmma::load_matrix_sync(b, Bs + ks * 8 * LDB + wn * 64 + nt * 16, LDB);
                #pragma unroll
                for (int i = 0; i < b.num_elements; i++) b.x[i] = wmma::__float_to_tf32(b.x[i]);
                wmma::mma_sync(c[nt], a, b, c[nt]);
            }
        }
        __syncthreads();
    }

    #pragma unroll
    for (int nt = 0; nt < 4; nt++)
        wmma::store_matrix_sync(Cs + wm * 16 * LDC + wn * 64 + nt * 16, c[nt], LDC, wmma::mem_row_major);
    __syncthreads();

    float* dst = (y == 0) ? g_rg : (y == 1) ? g_zg : (y == 2) ? g_gin : g_ghn;

    #pragma unroll
    for (int x = 0; x < 8; x++) {
        int e = tid + x * 256;
        int r = e >> 5, j4 = (e & 31) * 4;
        int grow = n0 + r;
        if (grow < N_NODES) {
            float4 v = *reinterpret_cast<const float4*>(Cs + r * LDC + j4);
            float4 bb;
            if (y < 2) {
                float4 bi = *reinterpret_cast<const float4*>(b_ih + y * D + j4);
                float4 bh = *reinterpret_cast<const float4*>(b_hh + y * D + j4);
                bb = make_float4(bi.x + bh.x, bi.y + bh.y, bi.z + bh.z, bi.w + bh.w);
            } else if (y == 2) {
                bb = *reinterpret_cast<const float4*>(b_ih + 2 * D + j4);
            } else {
                bb = *reinterpret_cast<const float4*>(b_hh + 2 * D + j4);
            }
            v.x += bb.x; v.y += bb.y; v.z += bb.z; v.w += bb.w;
            if (y < 2) {
                v.x = sigmoid_acc(v.x); v.y = sigmoid_acc(v.y);
                v.z = sigmoid_acc(v.z); v.w = sigmoid_acc(v.w);
            }
            *reinterpret_cast<float4*>(dst + (size_t)grow * D + j4) = v;
        }
    }
}

// ---------------- edge scatter: warp/edge, LDG.128 + red.v4 ------------------
__global__ void scatter_kernel(const int* __restrict__ esrc, const int* __restrict__ edst,
                               const int* __restrict__ etype) {
    long long gtid = (long long)blockIdx.x * blockDim.x + threadIdx.x;
    int e    = (int)(gtid >> 5);
    int lane = (int)(gtid & 31);
    if (e >= N_EDGES) return;
    int s  = esrc[e];
    int d2 = edst[e];
    int t  = etype[e];
    float4 v = *reinterpret_cast<const float4*>(
        g_tr + ((size_t)t * N_NODES + s) * D + lane * 4);
    float* out = g_a + (size_t)d2 * D + lane * 4;
    asm volatile("red.global.add.v4.f32 [%0], {%1, %2, %3, %4};"
                 :: "l"(out), "f"(v.x), "f"(v.y), "f"(v.z), "f"(v.w)
                 : "memory");
}

// ---------------- GRU combine: h = (1-z)*tanh(gin + r*ghn) + z*h -------------
__global__ void gru_combine_kernel() {
    int idx = blockIdx.x * blockDim.x + threadIdx.x;
    if (idx >= (N_NODES * D) / 4) return;
    float4 r  = reinterpret_cast<const float4*>(g_rg)[idx];
    float4 z  = reinterpret_cast<const float4*>(g_zg)[idx];
    float4 in = reinterpret_cast<const float4*>(g_gin)[idx];
    float4 hn = reinterpret_cast<const float4*>(g_ghn)[idx];
    float4 h  = reinterpret_cast<const float4*>(g_h)[idx];
    float4 o;
    o.x = (1.0f - z.x) * tanh_acc(in.x + r.x * hn.x) + z.x * h.x;
    o.y = (1.0f - z.y) * tanh_acc(in.y + r.y * hn.y) + z.y * h.y;
    o.z = (1.0f - z.z) * tanh_acc(in.z + r.z * hn.z) + z.z * h.z;
    o.w = (1.0f - z.w) * tanh_acc(in.w + r.w * hn.w) + z.w * h.w;
    reinterpret_cast<float4*>(g_h)[idx] = o;
}

// ---------------- pooling ----------------
__global__ void pool_kernel(const int* __restrict__ graph_ids) {
    int g = blockIdx.x;
    int d = threadIdx.x;
    int lo = 0, hi = N_NODES;
    while (lo < hi) { int mid = (lo + hi) >> 1; if (graph_ids[mid] < g) lo = mid + 1; else hi = mid; }
    int start = lo;
    hi = N_NODES;
    while (lo < hi) { int mid = (lo + hi) >> 1; if (graph_ids[mid] < g + 1) lo = mid + 1; else hi = mid; }
    int end = lo;
    float sum = 0.0f;
    for (int n = start; n < end; n++) sum += g_h[(size_t)n * D + d];
    float cnt = (float)(end - start);
    g_pooled[g * D + d] = sum / fmaxf(cnt, 1.0f);
}

// ---------------- classifier ----------------
__global__ void classifier_kernel(const float* __restrict__ W1, const float* __restrict__ b1,
                                  const float* __restrict__ W2, const float* __restrict__ b2,
                                  float* __restrict__ out) {
    __shared__ float ps[D];
    __shared__ float red[256];
    int g = blockIdx.x;
    int j = threadIdx.x;
    if (j < D) ps[j] = g_pooled[g * D + j];
    __syncthreads();
    float acc = 0.0f;
    const float* w = W1 + j * D;
    #pragma unroll 8
    for (int d = 0; d < D; d++) acc = fmaf(ps[d], w[d], acc);
    float hidden = fmaxf(acc + b1[j], 0.0f);
    red[j] = hidden * W2[j];
    __syncthreads();
    #pragma unroll
    for (int s = 128; s > 0; s >>= 1) {
        if (j < s) red[j] += red[j + s];
        __syncthreads();
    }
    if (j == 0) out[g] = sigmoid_acc(red[0] + b2[0]);
}

// ---------------- launch orchestration ----------------------------------------
extern "C" void kernel_launch(void* const* d_in, const int* in_sizes, int n_in,
                              void* d_out, int out_size) {
    const float* features  = (const float*)d_in[0];
    const int*   edge_src  = (const int*)  d_in[1];
    const int*   edge_dst  = (const int*)  d_in[2];
    const int*   edge_types= (const int*)  d_in[3];
    const int*   graph_ids = (const int*)  d_in[4];
    const float* W_msg     = (const float*)d_in[5];
    const float* b_msg     = (const float*)d_in[6];
    const float* W_ih      = (const float*)d_in[7];
    const float* W_hh      = (const float*)d_in[8];
    const float* b_ih      = (const float*)d_in[9];
    const float* b_hh      = (const float*)d_in[10];
    const float* W1        = (const float*)d_in[11];
    const float* b1        = (const float*)d_in[12];
    const float* W2        = (const float*)d_in[13];
    const float* b2        = (const float*)d_in[14];
    float* out = (float*)d_out;

    pad_h_kernel<<<(N_NODES * D + 255) / 256, 256>>>(features);
    transpose_ih_kernel<<<(G3 * D + 255) / 256, 256>>>(W_ih);
    transpose_hh_kernel<<<(G3 * D + 255) / 256, 256>>>(W_hh);

    const int SC_BLOCKS = (int)(((long long)N_EDGES * 32 + 255) / 256);
    const int CB_BLOCKS = (N_NODES * D / 4 + 255) / 256;

    for (int step = 0; step < N_STEPS; step++) {
        lin_msg_kernel<<<dim3(NBLK_G, 1, N_ETYPES), 256>>>(W_msg, b_msg);
        zero_a_kernel<<<(N_NODES * D / 4 + 255) / 256, 256>>>();
        scatter_kernel<<<SC_BLOCKS, 256>>>(edge_src, edge_dst, edge_types);
        gru_gates_kernel<<<dim3(NBLK_G, 4), 256>>>(b_ih, b_hh);
        gru_combine_kernel<<<CB_BLOCKS, 256>>>();
    }

    pool_kernel<<<N_GRAPHS, D>>>(graph_ids);
    classifier_kernel<<<N_GRAPHS, 256>>>(W1, b1, W2, b2, out);
}

// round 17
// speedup vs baseline: 2.3824x; 1.0493x over previous
#include <cuda_runtime.h>
#include <cuda_bf16.h>
#include <math.h>
#include <mma.h>

using namespace nvcuda;

#define N_NODES  50000
#define N_PAD    50048       // 391 * 128, pad rows so wmma stores never go OOB
#define N_EDGES  800000
#define N_GRAPHS 100
#define IN_DIM   100
#define D        128
#define N_ETYPES 4
#define N_STEPS  8
#define G3       384
#define NBLK     391         // N_PAD / 128

#define LDA 36               // 32 + 4
#define LDB 132              // 128 + 4

// ---------------- scratch (device symbols referenced ONLY in device code) ---
__device__ float g_h[(size_t)N_PAD * D];
__device__ float g_tr[(size_t)N_ETYPES * N_PAD * D];
__device__ float g_a[(size_t)N_PAD * D];
__device__ float g_Wm[(size_t)N_ETYPES * D * D];   // tf32-rounded W_msg
__device__ float g_WihT[D * G3];                   // tf32-rounded, transposed
__device__ float g_WhhT[D * G3];
__device__ float g_rg[(size_t)N_PAD * D];          // raw pre-activations
__device__ float g_zg[(size_t)N_PAD * D];
__device__ float g_gin[(size_t)N_PAD * D];
__device__ float g_ghn[(size_t)N_PAD * D];
__device__ float g_pooled[N_GRAPHS * D];

#define LOG2E 1.4426950408889634f

__device__ __forceinline__ float sigmoid_acc(float x) {
    return 1.0f / (1.0f + exp2f(-LOG2E * x));
}
__device__ __forceinline__ float tanh_acc(float x) {
    float xc = fminf(fmaxf(x, -20.0f), 20.0f);
    float t = exp2f(2.0f * LOG2E * xc);
    return (t - 1.0f) / (t + 1.0f);
}

// ---------------- init ----------------
__global__ void pad_h_kernel(const float* __restrict__ features) {
    int idx = blockIdx.x * blockDim.x + threadIdx.x;
    if (idx >= N_PAD * D) return;
    int n = idx >> 7;
    int d = idx & 127;
    g_h[idx] = (n < N_NODES && d < IN_DIM) ? features[n * IN_DIM + d] : 0.0f;
}

__global__ void zero_a_kernel() {
    int idx = blockIdx.x * blockDim.x + threadIdx.x;
    if (idx < (N_NODES * D) / 4)
        reinterpret_cast<float4*>(g_a)[idx] = make_float4(0.f, 0.f, 0.f, 0.f);
}

// W_msg -> tf32-rounded copy
__global__ void round_wmsg_kernel(const float* __restrict__ W) {
    int idx = blockIdx.x * blockDim.x + threadIdx.x;
    if (idx < N_ETYPES * D * D) g_Wm[idx] = wmma::__float_to_tf32(W[idx]);
}
// W [G3 x 128] -> transposed + tf32-rounded [128 x G3]
__global__ void transpose_ih_kernel(const float* __restrict__ W) {
    int idx = blockIdx.x * blockDim.x + threadIdx.x;
    if (idx >= G3 * D) return;
    int r = idx >> 7;
    int k = idx & 127;
    g_WihT[k * G3 + r] = wmma::__float_to_tf32(W[idx]);
}
__global__ void transpose_hh_kernel(const float* __restrict__ W) {
    int idx = blockIdx.x * blockDim.x + threadIdx.x;
    if (idx >= G3 * D) return;
    int r = idx >> 7;
    int k = idx & 127;
    g_WhhT[k * G3 + r] = wmma::__float_to_tf32(W[idx]);
}

// ---------------- msg GEMM: g_tr[t] = h @ Wm[t] + b_msg[t] -------------------
// 256 thr, tile 128x128, warps 4(M)x2(N), warp computes 32x64 (2x4 frags).
// Bias preloaded into accumulators; direct global store (rows padded).
__global__ __launch_bounds__(256) void lin_msg_kernel(const float* __restrict__ b_msg) {
    __shared__ float sm[128 * LDA + 32 * LDB];   // 8832 floats
    float* As = sm;                 // 128 x LDA
    float* Bs = sm + 128 * LDA;     // 32 x LDB (also bias staging)

    const int tid = threadIdx.x;
    const int t   = blockIdx.z;
    const int n0  = blockIdx.x * 128;
    const int w   = tid >> 5;
    const int wm  = w & 3;          // rows wm*32
    const int wn  = w >> 2;         // cols wn*64

    // bias -> 16 replicated rows in Bs, init accumulators from it
    #pragma unroll
    for (int x = 0; x < 8; x++) {
        int e = tid + x * 256;
        int r = e >> 7, j = e & 127;
        Bs[r * LDB + j] = b_msg[t * D + j];
    }
    __syncthreads();
    wmma::fragment<wmma::accumulator, 16, 16, 8, float> c[2][4];
    #pragma unroll
    for (int mf = 0; mf < 2; mf++)
        #pragma unroll
        for (int nt = 0; nt < 4; nt++)
            wmma::load_matrix_sync(c[mf][nt], Bs + wn * 64 + nt * 16, LDB, wmma::mem_row_major);
    __syncthreads();

    const float* Wt = g_Wm + (size_t)t * D * D;

    for (int kt = 0; kt < 4; kt++) {
        // stage A (tf32-rounded): 128x32 = 1024 f4, 4/thread
        #pragma unroll
        for (int x = 0; x < 4; x++) {
            int e = tid + x * 256;
            int r = e >> 3, kq = e & 7;
            int grow = n0 + r;
            float4 v = make_float4(0.f, 0.f, 0.f, 0.f);
            if (grow < N_NODES)
                v = *reinterpret_cast<const float4*>(g_h + (size_t)grow * D + kt * 32 + kq * 4);
            v.x = wmma::__float_to_tf32(v.x); v.y = wmma::__float_to_tf32(v.y);
            v.z = wmma::__float_to_tf32(v.z); v.w = wmma::__float_to_tf32(v.w);
            *reinterpret_cast<float4*>(As + r * LDA + kq * 4) = v;
        }
        // stage B (already tf32): 32x128 = 1024 f4, 4/thread
        #pragma unroll
        for (int x = 0; x < 4; x++) {
            int e = tid + x * 256;
            int k = e >> 5, j4 = (e & 31) * 4;
            *reinterpret_cast<float4*>(Bs + k * LDB + j4) =
                *reinterpret_cast<const float4*>(Wt + (size_t)(kt * 32 + k) * D + j4);
        }
        __syncthreads();

        #pragma unroll
        for (int ks = 0; ks < 4; ks++) {
            wmma::fragment<wmma::matrix_a, 16, 16, 8, wmma::precision::tf32, wmma::row_major> a[2];
            #pragma unroll
            for (int mf = 0; mf < 2; mf++)
                wmma::load_matrix_sync(a[mf], As + (wm * 32 + mf * 16) * LDA + ks * 8, LDA);
            #pragma unroll
            for (int nt = 0; nt < 4; nt++) {
                wmma::fragment<wmma::matrix_b, 16, 16, 8, wmma::precision::tf32, wmma::row_major> b;
                wmma::load_matrix_sync(b, Bs + ks * 8 * LDB + wn * 64 + nt * 16, LDB);
                wmma::mma_sync(c[0][nt], a[0], b, c[0][nt]);
                wmma::mma_sync(c[1][nt], a[1], b, c[1][nt]);
            }
        }
        __syncthreads();
    }

    float* C = g_tr + (size_t)t * N_PAD * D;
    #pragma unroll
    for (int mf = 0; mf < 2; mf++)
        #pragma unroll
        for (int nt = 0; nt < 4; nt++)
            wmma::store_matrix_sync(C + (size_t)(n0 + wm * 32 + mf * 16) * D + wn * 64 + nt * 16,
                                    c[mf][nt], D, wmma::mem_row_major);
}

// ---------------- GRU gates GEMM --------------------------------------------
// grid (NBLK, 4): y=0: rg_raw = [a|h]@[Wih;Whh]c0 + bi0+bh0 (K=256)
//                 y=1: zg_raw chunk1 (K=256)
//                 y=2: gin = a@Wih c2 + bi2 (K=128); y=3: ghn = h@Whh c2 + bh2
// Raw pre-activations stored; sigmoid applied in gru_combine.
__global__ __launch_bounds__(256) void gru_gates_kernel(
    const float* __restrict__ b_ih, const float* __restrict__ b_hh)
{
    __shared__ float sm[128 * LDA + 32 * LDB];
    float* As = sm;
    float* Bs = sm + 128 * LDA;

    const int tid = threadIdx.x;
    const int y   = blockIdx.y;
    const int n0  = blockIdx.x * 128;
    const int w   = tid >> 5;
    const int wm  = w & 3;
    const int wn  = w >> 2;

    #pragma unroll
    for (int x = 0; x < 8; x++) {
        int e = tid + x * 256;
        int r = e >> 7, j = e & 127;
        float bb;
        if (y == 0)      bb = b_ih[j] + b_hh[j];
        else if (y == 1) bb = b_ih[D + j] + b_hh[D + j];
        else if (y == 2) bb = b_ih[2 * D + j];
        else             bb = b_hh[2 * D + j];
        Bs[r * LDB + j] = bb;
    }
    __syncthreads();
    wmma::fragment<wmma::accumulator, 16, 16, 8, float> c[2][4];
    #pragma unroll
    for (int mf = 0; mf < 2; mf++)
        #pragma unroll
        for (int nt = 0; nt < 4; nt++)
            wmma::load_matrix_sync(c[mf][nt], Bs + wn * 64 + nt * 16, LDB, wmma::mem_row_major);
    __syncthreads();

    const int nkt = (y < 2) ? 8 : 4;
    for (int kt = 0; kt < nkt; kt++) {
        const float* Asrc;
        const float* Bsrc;
        int koff, bcol;
        if (y < 2) {
            Asrc = (kt < 4) ? g_a : g_h;
            Bsrc = (kt < 4) ? g_WihT : g_WhhT;
            koff = (kt & 3) * 32;
            bcol = y * D;
        } else {
            Asrc = (y == 2) ? g_a : g_h;
            Bsrc = (y == 2) ? g_WihT : g_WhhT;
            koff = kt * 32;
            bcol = 2 * D;
        }

        #pragma unroll
        for (int x = 0; x < 4; x++) {
            int e = tid + x * 256;
            int r = e >> 3, kq = e & 7;
            int grow = n0 + r;
            float4 v = make_float4(0.f, 0.f, 0.f, 0.f);
            if (grow < N_NODES)
                v = *reinterpret_cast<const float4*>(Asrc + (size_t)grow * D + koff + kq * 4);
            v.x = wmma::__float_to_tf32(v.x); v.y = wmma::__float_to_tf32(v.y);
            v.z = wmma::__float_to_tf32(v.z); v.w = wmma::__float_to_tf32(v.w);
            *reinterpret_cast<float4*>(As + r * LDA + kq * 4) = v;
        }
        #pragma unroll
        for (int x = 0; x < 4; x++) {
            int e = tid + x * 256;
            int k = e >> 5, j4 = (e & 31) * 4;
            *reinterpret_cast<float4*>(Bs + k * LDB + j4) =
                *reinterpret_cast<const float4*>(Bsrc + (size_t)(koff + k) * G3 + bcol + j4);
        }
        __syncthreads();

        #pragma unroll
        for (int ks = 0; ks < 4; ks++) {
            wmma::fragment<wmma::matrix_a, 16, 16, 8, wmma::precision::tf32, wmma::row_major> a[2];
            #pragma unroll
            for (int mf = 0; mf < 2; mf++)
                wmma::load_matrix_sync(a[mf], As + (wm * 32 + mf * 16) * LDA + ks * 8, LDA);
            #pragma unroll
            for (int nt = 0; nt < 4; nt++) {
                wmma::fragment<wmma::matrix_b, 16, 16, 8, wmma::precision::tf32, wmma::row_major> b;
                wmma::load_matrix_sync(b, Bs + ks * 8 * LDB + wn * 64 + nt * 16, LDB);
                wmma::mma_sync(c[0][nt], a[0], b, c[0][nt]);
                wmma::mma_sync(c[1][nt], a[1], b, c[1][nt]);
            }
        }
        __syncthreads();
    }

    float* dst = (y == 0) ? g_rg : (y == 1) ? g_zg : (y == 2) ? g_gin : g_ghn;
    #pragma unroll
    for (int mf = 0; mf < 2; mf++)
        #pragma unroll
        for (int nt = 0; nt < 4; nt++)
            wmma::store_matrix_sync(dst + (size_t)(n0 + wm * 32 + mf * 16) * D + wn * 64 + nt * 16,
                                    c[mf][nt], D, wmma::mem_row_major);
}

// ---------------- edge scatter: warp/edge, LDG.128 + red.v4 ------------------
__global__ void scatter_kernel(const int* __restrict__ esrc, const int* __restrict__ edst,
                               const int* __restrict__ etype) {
    long long gtid = (long long)blockIdx.x * blockDim.x + threadIdx.x;
    int e    = (int)(gtid >> 5);
    int lane = (int)(gtid & 31);
    if (e >= N_EDGES) return;
    int s  = esrc[e];
    int d2 = edst[e];
    int t  = etype[e];
    float4 v = *reinterpret_cast<const float4*>(
        g_tr + ((size_t)t * N_PAD + s) * D + lane * 4);
    float* out = g_a + (size_t)d2 * D + lane * 4;
    asm volatile("red.global.add.v4.f32 [%0], {%1, %2, %3, %4};"
                 :: "l"(out), "f"(v.x), "f"(v.y), "f"(v.z), "f"(v.w)
                 : "memory");
}

// ---------------- GRU combine: sigmoid applied here ---------------------------
__global__ void gru_combine_kernel() {
    int idx = blockIdx.x * blockDim.x + threadIdx.x;
    if (idx >= (N_NODES * D) / 4) return;
    float4 rr = reinterpret_cast<const float4*>(g_rg)[idx];
    float4 zz = reinterpret_cast<const float4*>(g_zg)[idx];
    float4 in = reinterpret_cast<const float4*>(g_gin)[idx];
    float4 hn = reinterpret_cast<const float4*>(g_ghn)[idx];
    float4 h  = reinterpret_cast<const float4*>(g_h)[idx];
    float4 o;
    float r, z;
    r = sigmoid_acc(rr.x); z = sigmoid_acc(zz.x);
    o.x = (1.0f - z) * tanh_acc(in.x + r * hn.x) + z * h.x;
    r = sigmoid_acc(rr.y); z = sigmoid_acc(zz.y);
    o.y = (1.0f - z) * tanh_acc(in.y + r * hn.y) + z * h.y;
    r = sigmoid_acc(rr.z); z = sigmoid_acc(zz.z);
    o.z = (1.0f - z) * tanh_acc(in.z + r * hn.z) + z * h.z;
    r = sigmoid_acc(rr.w); z = sigmoid_acc(zz.w);
    o.w = (1.0f - z) * tanh_acc(in.w + r * hn.w) + z * h.w;
    reinterpret_cast<float4*>(g_h)[idx] = o;
}

// ---------------- pooling ----------------
__global__ void pool_kernel(const int* __restrict__ graph_ids) {
    int g = blockIdx.x;
    int d = threadIdx.x;
    int lo = 0, hi = N_NODES;
    while (lo < hi) { int mid = (lo + hi) >> 1; if (graph_ids[mid] < g) lo = mid + 1; else hi = mid; }
    int start = lo;
    hi = N_NODES;
    while (lo < hi) { int mid = (lo + hi) >> 1; if (graph_ids[mid] < g + 1) lo = mid + 1; else hi = mid; }
    int end = lo;
    float sum = 0.0f;
    for (int n = start; n < end; n++) sum += g_h[(size_t)n * D + d];
    float cnt = (float)(end - start);
    g_pooled[g * D + d] = sum / fmaxf(cnt, 1.0f);
}

// ---------------- classifier ----------------
__global__ void classifier_kernel(const float* __restrict__ W1, const float* __restrict__ b1,
                                  const float* __restrict__ W2, const float* __restrict__ b2,
                                  float* __restrict__ out) {
    __shared__ float ps[D];
    __shared__ float red[256];
    int g = blockIdx.x;
    int j = threadIdx.x;
    if (j < D) ps[j] = g_pooled[g * D + j];
    __syncthreads();
    float acc = 0.0f;
    const float* w = W1 + j * D;
    #pragma unroll 8
    for (int d = 0; d < D; d++) acc = fmaf(ps[d], w[d], acc);
    float hidden = fmaxf(acc + b1[j], 0.0f);
    red[j] = hidden * W2[j];
    __syncthreads();
    #pragma unroll
    for (int s = 128; s > 0; s >>= 1) {
        if (j < s) red[j] += red[j + s];
        __syncthreads();
    }
    if (j == 0) out[g] = sigmoid_acc(red[0] + b2[0]);
}

// ---------------- launch orchestration ----------------------------------------
extern "C" void kernel_launch(void* const* d_in, const int* in_sizes, int n_in,
                              void* d_out, int out_size) {
    const float* features  = (const float*)d_in[0];
    const int*   edge_src  = (const int*)  d_in[1];
    const int*   edge_dst  = (const int*)  d_in[2];
    const int*   edge_types= (const int*)  d_in[3];
    const int*   graph_ids = (const int*)  d_in[4];
    const float* W_msg     = (const float*)d_in[5];
    const float* b_msg     = (const float*)d_in[6];
    const float* W_ih      = (const float*)d_in[7];
    const float* W_hh      = (const float*)d_in[8];
    const float* b_ih      = (const float*)d_in[9];
    const float* b_hh      = (const float*)d_in[10];
    const float* W1        = (const float*)d_in[11];
    const float* b1        = (const float*)d_in[12];
    const float* W2        = (const float*)d_in[13];
    const float* b2        = (const float*)d_in[14];
    float* out = (float*)d_out;

    pad_h_kernel<<<(N_PAD * D + 255) / 256, 256>>>(features);
    round_wmsg_kernel<<<(N_ETYPES * D * D + 255) / 256, 256>>>(W_msg);
    transpose_ih_kernel<<<(G3 * D + 255) / 256, 256>>>(W_ih);
    transpose_hh_kernel<<<(G3 * D + 255) / 256, 256>>>(W_hh);

    const int SC_BLOCKS = (int)(((long long)N_EDGES * 32 + 255) / 256);
    const int CB_BLOCKS = (N_NODES * D / 4 + 255) / 256;

    for (int step = 0; step < N_STEPS; step++) {
        lin_msg_kernel<<<dim3(NBLK, 1, N_ETYPES), 256>>>(b_msg);
        zero_a_kernel<<<(N_NODES * D / 4 + 255) / 256, 256>>>();
        scatter_kernel<<<SC_BLOCKS, 256>>>(edge_src, edge_dst, edge_types);
        gru_gates_kernel<<<dim3(NBLK, 4), 256>>>(b_ih, b_hh);
        gru_combine_kernel<<<CB_BLOCKS, 256>>>();
    }

    pool_kernel<<<N_GRAPHS, D>>>(graph_ids);
    classifier_kernel<<<N_GRAPHS, 256>>>(W1, b1, W2, b2, out);
}